// round 12
// baseline (speedup 1.0000x reference)
#include <cuda_runtime.h>
#include <cuda_fp16.h>
#include <cstdint>

#define B_  8
#define D_  256
#define T_  2048
#define K_  8192
#define BT_ (B_ * T_)
#define ZQ_ELEMS (BT_ * D_)

// ---------------- device scratch ----------------
__device__ __half g_zhi[BT_ * D_];   // [m][d] fp16 hi of z
__device__ __half g_zlo[BT_ * D_];   // [m][d] fp16 lo of z
__device__ __half g_chi[K_ * D_];    // [n][d] fp16 hi of 512*cb
__device__ __half g_clo[K_ * D_];    // [n][d] fp16 lo of 512*cb
__device__ float g_s1[BT_];
__device__ float g_s2[K_];
__device__ unsigned long long g_best[BT_];
__device__ double g_loss;

#define CP16(sa, ga) asm volatile("cp.async.cg.shared.global [%0], [%1], 16;" \
    :: "r"((uint32_t)(sa)), "l"(ga) : "memory")
#define CP_COMMIT()  asm volatile("cp.async.commit_group;" ::: "memory")

__device__ __forceinline__ uint32_t smem_u32(const void* p) {
    uint32_t a;
    asm("{ .reg .u64 t; cvta.to.shared.u64 t, %1; cvt.u32.u64 %0, t; }"
        : "=r"(a) : "l"(p));
    return a;
}

#define LDM4(r, addr) \
    asm volatile("ldmatrix.sync.aligned.m8n8.x4.shared.b16 {%0,%1,%2,%3}, [%4];" \
        : "=r"((r)[0]), "=r"((r)[1]), "=r"((r)[2]), "=r"((r)[3]) : "r"(addr))

// ---------------- init ----------------
__global__ void init_kernel() {
    int i = blockIdx.x * blockDim.x + threadIdx.x;
    if (i < BT_) g_best[i] = 0xFFFFFFFFFFFFFFFFULL;
    if (i == 0)  g_loss = 0.0;
}

// ------- split codebook (x512) -> fp16 hi/lo [K][D] + s2 -------
__global__ void split_cb_kernel(const float* __restrict__ cb) {
    int w = threadIdx.x >> 5, lane = threadIdx.x & 31;
    int n = blockIdx.x * 8 + w;
    size_t base = (size_t)n * D_;
    double s = 0.0;
    #pragma unroll
    for (int i = 0; i < 8; i++) {
        float v = cb[base + lane + 32 * i];
        s += (double)v * v;
        float vs = v * 512.0f;                 // exact
        __half hi = __float2half_rn(vs);
        float hif = __half2float(hi);          // exact
        __half lo = __float2half_rn(vs - hif);
        g_chi[base + lane + 32 * i] = hi;
        g_clo[base + lane + 32 * i] = lo;
    }
    #pragma unroll
    for (int o = 16; o; o >>= 1) s += __shfl_xor_sync(0xffffffffu, s, o);
    if (lane == 0) g_s2[n] = (float)s;
}

// ------- split z -> fp16 hi/lo [m][d] + s1 -------
__global__ void split_z_kernel(const float* __restrict__ z) {
    __shared__ float  sz[32][257];
    __shared__ double sred[8][33];
    int m0 = blockIdx.x * 32;
    int b  = m0 >> 11;
    int t0 = m0 & 2047;
    int tt = threadIdx.x & 31;
    int dp = threadIdx.x >> 5;
    double s = 0.0;
    #pragma unroll
    for (int di = 0; di < 32; di++) {
        int d = dp * 32 + di;
        float v = z[((size_t)b * D_ + d) * T_ + t0 + tt];
        sz[tt][d] = v;
        s += (double)v * v;
    }
    sred[dp][tt] = s;
    __syncthreads();
    if (dp == 0) {
        double tot = 0.0;
        #pragma unroll
        for (int p = 0; p < 8; p++) tot += sred[p][tt];
        g_s1[m0 + tt] = (float)tot;
    }
    #pragma unroll
    for (int r8 = 0; r8 < 4; r8++) {
        int row = dp * 4 + r8;
        size_t base = (size_t)(m0 + row) * D_;
        #pragma unroll
        for (int i = 0; i < 8; i++) {
            int d = tt + 32 * i;
            float v  = sz[row][d];
            __half hi = __float2half_rn(v);
            float hif = __half2float(hi);
            __half lo = __float2half_rn(v - hif);
            g_zhi[base + d] = hi;
            g_zlo[base + d] = lo;
        }
    }
}

// ---------------- dist: fp16 mma 3-pass, 4-stage single-barrier pipe ----------
// CTA 128m x 128n, BK=16, 16 chunks, 4 stages. One __syncthreads per chunk.
#define SROW 24                      // halves per row (48B: 16B-aligned, phases ok)
#define MATB (128 * SROW * 2)        // 6144 B per matrix per stage
#define STB  (4 * MATB)              // 24576 B per stage
#define NST  4
#define SMEM_BYTES (NST * STB)       // 98304 per CTA
#define NCH  16                      // k-chunks per tile

__device__ __forceinline__ void mma_fp16(float* c, const uint32_t* a,
                                         uint32_t b0, uint32_t b1) {
    asm("mma.sync.aligned.m16n8k16.row.col.f32.f16.f16.f32 "
        "{%0,%1,%2,%3}, {%4,%5,%6,%7}, {%8,%9}, {%0,%1,%2,%3};"
        : "+f"(c[0]), "+f"(c[1]), "+f"(c[2]), "+f"(c[3])
        : "r"(a[0]), "r"(a[1]), "r"(a[2]), "r"(a[3]), "r"(b0), "r"(b1));
}

__global__ void __launch_bounds__(256, 2)
dist_mma_kernel() {
    extern __shared__ char smem[];
    uint32_t sbase = smem_u32(smem);

    int tid  = threadIdx.x;
    int wid  = tid >> 5, lane = tid & 31;
    int g    = lane >> 2;
    int tig  = lane & 3;
    int wm   = wid >> 1;       // 0..3
    int wn   = wid & 1;        // 0..1
    int m0   = blockIdx.y * 128;
    int n0   = blockIdx.x * 128;

    // ldmatrix lane offsets (16 rows x 16 halves per x4)
    int aRow = (lane & 7) + ((lane >> 3) & 1) * 8;
    int aK   = (lane >> 4) * 8;
    int bRow = (lane & 7) + (lane >> 4) * 8;
    int bK   = ((lane >> 3) & 1) * 8;
    uint32_t offA0 = (uint32_t)((wm * 32 + aRow) * SROW + aK) * 2;
    uint32_t offA1 = offA0 + 16 * SROW * 2;
    uint32_t offB  = (uint32_t)((wn * 64 + bRow) * SROW + bK) * 2;

    // cp.async: 1 CP16 per matrix per thread. row = tid>>1, q = tid&1.
    int srow = tid >> 1, sq = tid & 1;
    uint32_t so = (uint32_t)(srow * SROW + sq * 8) * 2;
    const __half* pA = g_zhi + (size_t)(m0 + srow) * D_ + sq * 8;
    const __half* pB = g_chi + (size_t)(n0 + srow) * D_ + sq * 8;
    const ptrdiff_t LOO = (ptrdiff_t)BT_ * D_;
    const ptrdiff_t LOC = (ptrdiff_t)K_ * D_;

    float acc[2][8][4];
    #pragma unroll
    for (int mt = 0; mt < 2; mt++)
        #pragma unroll
        for (int nt = 0; nt < 8; nt++)
            #pragma unroll
            for (int q = 0; q < 4; q++) acc[mt][nt][q] = 0.0f;

    #define ISSUE_CHUNK(it2) do {                                            \
        uint32_t s0 = sbase + ((it2) & 3) * STB;                              \
        ptrdiff_t dd = (ptrdiff_t)((it2) * 16);                               \
        CP16(s0 + so,            pA + dd);                                    \
        CP16(s0 + MATB + so,     pA + LOO + dd);                              \
        CP16(s0 + 2 * MATB + so, pB + dd);                                    \
        CP16(s0 + 3 * MATB + so, pB + LOC + dd);                              \
        CP_COMMIT();                                                          \
    } while (0)

    ISSUE_CHUNK(0);
    ISSUE_CHUNK(1);
    ISSUE_CHUNK(2);

    for (int it = 0; it < NCH; it++) {
        // wait until chunk `it` has landed (outstanding groups: min(3, NCH-it))
        if (it < NCH - 2)      asm volatile("cp.async.wait_group 2;" ::: "memory");
        else if (it == NCH - 2) asm volatile("cp.async.wait_group 1;" ::: "memory");
        else                   asm volatile("cp.async.wait_group 0;" ::: "memory");
        __syncthreads();
        // stage (it+3)%4 == (it-1)%4 was fully consumed last iteration
        if (it + 3 < NCH) ISSUE_CHUNK(it + 3);

        uint32_t mAh = sbase + (it & 3) * STB;
        uint32_t mAl = mAh + MATB;
        uint32_t mBh = mAh + 2 * MATB;
        uint32_t mBl = mAh + 3 * MATB;

        uint32_t ah[2][4], al[2][4], bb[4][4];
        #pragma unroll
        for (int p = 0; p < 4; p++)
            LDM4(bb[p], mBh + offB + (uint32_t)(p * 16 * SROW) * 2);
        LDM4(ah[0], mAh + offA0);
        LDM4(ah[1], mAh + offA1);

        // pass 1: hi*hi (A-lo loads interleaved)
        mma_fp16(acc[0][0], ah[0], bb[0][0], bb[0][1]);
        mma_fp16(acc[1][0], ah[1], bb[0][0], bb[0][1]);
        mma_fp16(acc[0][1], ah[0], bb[0][2], bb[0][3]);
        mma_fp16(acc[1][1], ah[1], bb[0][2], bb[0][3]);
        LDM4(al[0], mAl + offA0);
        mma_fp16(acc[0][2], ah[0], bb[1][0], bb[1][1]);
        mma_fp16(acc[1][2], ah[1], bb[1][0], bb[1][1]);
        mma_fp16(acc[0][3], ah[0], bb[1][2], bb[1][3]);
        mma_fp16(acc[1][3], ah[1], bb[1][2], bb[1][3]);
        LDM4(al[1], mAl + offA1);
        #pragma unroll
        for (int p = 2; p < 4; p++) {
            mma_fp16(acc[0][2 * p],     ah[0], bb[p][0], bb[p][1]);
            mma_fp16(acc[1][2 * p],     ah[1], bb[p][0], bb[p][1]);
            mma_fp16(acc[0][2 * p + 1], ah[0], bb[p][2], bb[p][3]);
            mma_fp16(acc[1][2 * p + 1], ah[1], bb[p][2], bb[p][3]);
        }
        // pass 2: lo*hi; overwrite Bh[p] with B-lo[p] after last use
        #pragma unroll
        for (int p = 0; p < 4; p++) {
            mma_fp16(acc[0][2 * p],     al[0], bb[p][0], bb[p][1]);
            mma_fp16(acc[1][2 * p],     al[1], bb[p][0], bb[p][1]);
            mma_fp16(acc[0][2 * p + 1], al[0], bb[p][2], bb[p][3]);
            mma_fp16(acc[1][2 * p + 1], al[1], bb[p][2], bb[p][3]);
            LDM4(bb[p], mBl + offB + (uint32_t)(p * 16 * SROW) * 2);
        }
        // pass 3: hi*lo
        #pragma unroll
        for (int p = 0; p < 4; p++) {
            mma_fp16(acc[0][2 * p],     ah[0], bb[p][0], bb[p][1]);
            mma_fp16(acc[1][2 * p],     ah[1], bb[p][0], bb[p][1]);
            mma_fp16(acc[0][2 * p + 1], ah[0], bb[p][2], bb[p][3]);
            mma_fp16(acc[1][2 * p + 1], ah[1], bb[p][2], bb[p][3]);
        }
    }

    // ----- epilogue: acc = 512*dot; exact /512 via fma; reference grid -----
    #pragma unroll
    for (int mt = 0; mt < 2; mt++) {
        int row0 = m0 + wm * 32 + mt * 16 + g;
        int row1 = row0 + 8;
        float s1a = g_s1[row0];
        float s1b = g_s1[row1];
        unsigned long long k0 = 0xFFFFFFFFFFFFFFFFULL;
        unsigned long long k1 = 0xFFFFFFFFFFFFFFFFULL;
        #pragma unroll
        for (int nt = 0; nt < 8; nt++) {
            int nb = n0 + wn * 64 + nt * 8 + 2 * tig;
            #pragma unroll
            for (int q = 0; q < 2; q++) {
                int n = nb + q;
                float s2v = __ldg(&g_s2[n]);
                {
                    float f = __fmaf_rn(-0.00390625f, acc[mt][nt][q], s1a) + s2v;
                    unsigned u = __float_as_uint(f);
                    u = (u & 0x80000000u) ? ~u : (u | 0x80000000u);
                    unsigned long long key = ((unsigned long long)u << 32) | (unsigned)n;
                    k0 = k0 < key ? k0 : key;
                }
                {
                    float f = __fmaf_rn(-0.00390625f, acc[mt][nt][q + 2], s1b) + s2v;
                    unsigned u = __float_as_uint(f);
                    u = (u & 0x80000000u) ? ~u : (u | 0x80000000u);
                    unsigned long long key = ((unsigned long long)u << 32) | (unsigned)n;
                    k1 = k1 < key ? k1 : key;
                }
            }
        }
        #pragma unroll
        for (int o = 1; o <= 2; o <<= 1) {
            unsigned long long t0 = __shfl_xor_sync(0xffffffffu, k0, o);
            unsigned long long t1 = __shfl_xor_sync(0xffffffffu, k1, o);
            k0 = k0 < t0 ? k0 : t0;
            k1 = k1 < t1 ? k1 : t1;
        }
        if (tig == 0) {
            atomicMin(&g_best[row0], k0);
            atomicMin(&g_best[row1], k1);
        }
    }
}

// ---------------- gather z_q_st, indices, loss ----------------
__global__ void gather_kernel(const float* __restrict__ z,
                              const float* __restrict__ cb,
                              float* __restrict__ out, int out_size) {
    __shared__ float sm[32][257];
    __shared__ int   sidx[32];
    __shared__ double ssum[8];
    int m0 = blockIdx.x * 32;
    int b  = m0 >> 11;
    int t0 = m0 & 2047;
    int tid = threadIdx.x;

    if (tid < 32) {
        int idx = (int)(g_best[m0 + tid] & 0xFFFFFFFFULL);
        sidx[tid] = idx;
        if (out_size >= ZQ_ELEMS + BT_)
            out[ZQ_ELEMS + m0 + tid] = (float)idx;
    }
    __syncthreads();
    for (int r = 0; r < 32; r++)
        sm[r][tid] = cb[(size_t)sidx[r] * D_ + tid];
    __syncthreads();

    int tt = tid & 31, dp = tid >> 5;
    double lsum = 0.0;
    #pragma unroll 4
    for (int it = 0; it < 32; it++) {
        int d = dp * 32 + it;
        size_t oi = ((size_t)b * D_ + d) * T_ + t0 + tt;
        float zq = sm[tt][d];
        float zv = z[oi];
        float r  = zq - zv;
        out[oi]  = zv + r;
        lsum += (double)r * r;
    }
    #pragma unroll
    for (int o = 16; o; o >>= 1) lsum += __shfl_xor_sync(0xffffffffu, lsum, o);
    if (tt == 0) ssum[dp] = lsum;
    __syncthreads();
    if (tid == 0) {
        double tot = 0.0;
        #pragma unroll
        for (int p = 0; p < 8; p++) tot += ssum[p];
        atomicAdd(&g_loss, tot);
    }
}

__global__ void finalize_kernel(float* __restrict__ out, int out_size) {
    if (out_size >= ZQ_ELEMS + BT_ + 1)
        out[ZQ_ELEMS + BT_] = (float)(1.1 * g_loss / (double)ZQ_ELEMS);
}

// ---------------- launch ----------------
extern "C" void kernel_launch(void* const* d_in, const int* in_sizes, int n_in,
                              void* d_out, int out_size) {
    const float* z  = (const float*)d_in[0];
    const float* cb = (const float*)d_in[1];
    if (n_in >= 2 && in_sizes[0] == K_ * D_ && in_sizes[1] == ZQ_ELEMS) {
        const float* t = z; z = cb; cb = t;
    }
    float* out = (float*)d_out;

    cudaFuncSetAttribute(dist_mma_kernel,
                         cudaFuncAttributeMaxDynamicSharedMemorySize, SMEM_BYTES);

    init_kernel<<<(BT_ + 255) / 256, 256>>>();
    split_cb_kernel<<<K_ / 8, 256>>>(cb);
    split_z_kernel<<<BT_ / 32, 256>>>(z);

    dim3 grid(K_ / 128, BT_ / 128);   // (64, 128) = 8192 CTAs
    dist_mma_kernel<<<grid, 256, SMEM_BYTES>>>();

    gather_kernel<<<BT_ / 32, 256>>>(z, cb, out, out_size);
    finalize_kernel<<<1, 1>>>(out, out_size);
}

// round 13
// speedup vs baseline: 1.1652x; 1.1652x over previous
#include <cuda_runtime.h>
#include <cuda_fp16.h>
#include <cstdint>

#define B_  8
#define D_  256
#define T_  2048
#define K_  8192
#define BT_ (B_ * T_)
#define ZQ_ELEMS (BT_ * D_)

// ---------------- device scratch ----------------
__device__ __half g_zhi[BT_ * D_];   // [m][d] fp16 hi of z
__device__ __half g_zlo[BT_ * D_];   // [m][d] fp16 lo of z
__device__ __half g_chi[K_ * D_];    // [n][d] fp16 hi of 512*cb
__device__ __half g_clo[K_ * D_];    // [n][d] fp16 lo of 512*cb
__device__ float g_s1[BT_];
__device__ float g_s2[K_];
__device__ unsigned long long g_best[BT_];
__device__ double g_loss;

#define CP16(sa, ga) asm volatile("cp.async.cg.shared.global [%0], [%1], 16;" \
    :: "r"((uint32_t)(sa)), "l"(ga) : "memory")
#define CP_COMMIT()  asm volatile("cp.async.commit_group;" ::: "memory")

__device__ __forceinline__ uint32_t smem_u32(const void* p) {
    uint32_t a;
    asm("{ .reg .u64 t; cvta.to.shared.u64 t, %1; cvt.u32.u64 %0, t; }"
        : "=r"(a) : "l"(p));
    return a;
}

#define LDM4(r, addr) \
    asm volatile("ldmatrix.sync.aligned.m8n8.x4.shared.b16 {%0,%1,%2,%3}, [%4];" \
        : "=r"((r)[0]), "=r"((r)[1]), "=r"((r)[2]), "=r"((r)[3]) : "r"(addr))

// ------- split codebook (x512) -> fp16 hi/lo [K][D] + s2 (+g_loss init) -------
__global__ void split_cb_kernel(const float* __restrict__ cb) {
    if (blockIdx.x == 0 && threadIdx.x == 0) g_loss = 0.0;
    int w = threadIdx.x >> 5, lane = threadIdx.x & 31;
    int n = blockIdx.x * 8 + w;
    size_t base = (size_t)n * D_;
    double s = 0.0;
    #pragma unroll
    for (int i = 0; i < 8; i++) {
        float v = cb[base + lane + 32 * i];
        s += (double)v * v;
        float vs = v * 512.0f;                 // exact
        __half hi = __float2half_rn(vs);
        float hif = __half2float(hi);          // exact
        __half lo = __float2half_rn(vs - hif);
        g_chi[base + lane + 32 * i] = hi;
        g_clo[base + lane + 32 * i] = lo;
    }
    #pragma unroll
    for (int o = 16; o; o >>= 1) s += __shfl_xor_sync(0xffffffffu, s, o);
    if (lane == 0) g_s2[n] = (float)s;
}

// ------- split z -> fp16 hi/lo [m][d] + s1 (+g_best init) -------
__global__ void split_z_kernel(const float* __restrict__ z) {
    __shared__ float  sz[32][257];
    __shared__ double sred[8][33];
    int m0 = blockIdx.x * 32;
    int b  = m0 >> 11;
    int t0 = m0 & 2047;
    int tt = threadIdx.x & 31;
    int dp = threadIdx.x >> 5;
    if (dp == 0) g_best[m0 + tt] = 0xFFFFFFFFFFFFFFFFULL;
    double s = 0.0;
    #pragma unroll
    for (int di = 0; di < 32; di++) {
        int d = dp * 32 + di;
        float v = z[((size_t)b * D_ + d) * T_ + t0 + tt];
        sz[tt][d] = v;
        s += (double)v * v;
    }
    sred[dp][tt] = s;
    __syncthreads();
    if (dp == 0) {
        double tot = 0.0;
        #pragma unroll
        for (int p = 0; p < 8; p++) tot += sred[p][tt];
        g_s1[m0 + tt] = (float)tot;
    }
    #pragma unroll
    for (int r8 = 0; r8 < 4; r8++) {
        int row = dp * 4 + r8;
        size_t base = (size_t)(m0 + row) * D_;
        #pragma unroll
        for (int i = 0; i < 8; i++) {
            int d = tt + 32 * i;
            float v  = sz[row][d];
            __half hi = __float2half_rn(v);
            float hif = __half2float(hi);
            __half lo = __float2half_rn(v - hif);
            g_zhi[base + d] = hi;
            g_zlo[base + d] = lo;
        }
    }
}

// ---------------- dist: fp16 mma 3-pass, 3-stage single-barrier pipe ----------
// CTA 128m x 128n, BK=32, 8 chunks, 3 stages, ONE __syncthreads per chunk.
// Swizzled smem: 64B rows, unit (r,q) at r*64 + ((q ^ ((r>>1)&3))<<4).
#define MATB 8192                     // 128 rows * 64 B
#define STB  (4 * MATB)               // 32768 per stage
#define NST  3
#define SMEM_BYTES (NST * STB)        // 98304
#define NCH  8

__device__ __forceinline__ void mma_fp16(float* c, const uint32_t* a,
                                         uint32_t b0, uint32_t b1) {
    asm("mma.sync.aligned.m16n8k16.row.col.f32.f16.f16.f32 "
        "{%0,%1,%2,%3}, {%4,%5,%6,%7}, {%8,%9}, {%0,%1,%2,%3};"
        : "+f"(c[0]), "+f"(c[1]), "+f"(c[2]), "+f"(c[3])
        : "r"(a[0]), "r"(a[1]), "r"(a[2]), "r"(a[3]), "r"(b0), "r"(b1));
}

__global__ void __launch_bounds__(256, 2)
dist_mma_kernel() {
    extern __shared__ char smem[];
    uint32_t sbase = smem_u32(smem);

    int tid  = threadIdx.x;
    int wid  = tid >> 5, lane = tid & 31;
    int g    = lane >> 2;
    int tig  = lane & 3;
    int wm   = wid >> 1;       // 0..3
    int wn   = wid & 1;        // 0..1
    int m0   = blockIdx.y * 128;
    int n0   = blockIdx.x * 128;

    // ---- ldmatrix swizzled per-lane offsets ----
    int aRow = (lane & 7) + ((lane >> 3) & 1) * 8;   // 0..15
    int u0A  = lane >> 4;                             // k-unit 0/1
    int swA  = (aRow >> 1) & 3;
    int bRow = (lane & 7) + (lane >> 4) * 8;          // 0..15
    int ub0  = (lane >> 3) & 1;
    int swB  = (bRow >> 1) & 3;
    // offsets for ks=0 and ks=16 (k-unit +0 / +2)
    uint32_t offA_k[2], offB_k[2];
    offA_k[0] = (uint32_t)((wm * 32 + aRow) * 64 + (((u0A + 0) ^ swA) << 4));
    offA_k[1] = (uint32_t)((wm * 32 + aRow) * 64 + (((u0A + 2) ^ swA) << 4));
    offB_k[0] = (uint32_t)((wn * 64 + bRow) * 64 + (((ub0 + 0) ^ swB) << 4));
    offB_k[1] = (uint32_t)((wn * 64 + bRow) * 64 + (((ub0 + 2) ^ swB) << 4));
    // mt / nt-pair steps: +16 rows = +1024 B (swizzle invariant mod 16 rows)

    // ---- cp.async swizzled offsets: thread -> (srow, q = 2*(tid&1)+j) ----
    int srow = tid >> 1;
    int swS  = (srow >> 1) & 3;
    uint32_t soq[2];
    int q0 = (tid & 1) * 2;
    soq[0] = (uint32_t)(srow * 64 + (((q0 + 0) ^ swS) << 4));
    soq[1] = (uint32_t)(srow * 64 + (((q0 + 1) ^ swS) << 4));
    const __half* pA = g_zhi + (size_t)(m0 + srow) * D_ + q0 * 8;
    const __half* pB = g_chi + (size_t)(n0 + srow) * D_ + q0 * 8;
    const ptrdiff_t LOO = (ptrdiff_t)BT_ * D_;
    const ptrdiff_t LOC = (ptrdiff_t)K_ * D_;

    float acc[2][8][4];
    #pragma unroll
    for (int mt = 0; mt < 2; mt++)
        #pragma unroll
        for (int nt = 0; nt < 8; nt++)
            #pragma unroll
            for (int q = 0; q < 4; q++) acc[mt][nt][q] = 0.0f;

    #define ISSUE_CHUNK(it2, stg) do {                                       \
        uint32_t s0 = sbase + (stg) * STB;                                    \
        ptrdiff_t dd = (ptrdiff_t)((it2) * 32);                               \
        CP16(s0 + soq[0],            pA + dd);                                \
        CP16(s0 + soq[1],            pA + dd + 8);                            \
        CP16(s0 + MATB + soq[0],     pA + LOO + dd);                          \
        CP16(s0 + MATB + soq[1],     pA + LOO + dd + 8);                      \
        CP16(s0 + 2 * MATB + soq[0], pB + dd);                                \
        CP16(s0 + 2 * MATB + soq[1], pB + dd + 8);                            \
        CP16(s0 + 3 * MATB + soq[0], pB + LOC + dd);                          \
        CP16(s0 + 3 * MATB + soq[1], pB + LOC + dd + 8);                      \
        CP_COMMIT();                                                          \
    } while (0)

    ISSUE_CHUNK(0, 0);
    ISSUE_CHUNK(1, 1);

    int stC = 0, stI = 2;   // compute stage, issue stage
    for (int it = 0; it < NCH; it++) {
        if (it < NCH - 1) asm volatile("cp.async.wait_group 1;" ::: "memory");
        else              asm volatile("cp.async.wait_group 0;" ::: "memory");
        __syncthreads();
        // stage stI finished compute at iteration it-1 (proven by barrier)
        if (it + 2 < NCH) ISSUE_CHUNK(it + 2, stI);

        uint32_t mAh = sbase + stC * STB;
        uint32_t mAl = mAh + MATB;
        uint32_t mBh = mAh + 2 * MATB;
        uint32_t mBl = mAh + 3 * MATB;

        #pragma unroll
        for (int kh = 0; kh < 2; kh++) {
            uint32_t oA = offA_k[kh], oB = offB_k[kh];
            uint32_t ah[2][4], al[2][4], bb[4][4];
            #pragma unroll
            for (int p = 0; p < 4; p++)
                LDM4(bb[p], mBh + oB + (uint32_t)(p * 1024));
            LDM4(ah[0], mAh + oA);
            LDM4(ah[1], mAh + oA + 1024);

            // pass 1: hi*hi (A-lo loads interleaved)
            mma_fp16(acc[0][0], ah[0], bb[0][0], bb[0][1]);
            mma_fp16(acc[1][0], ah[1], bb[0][0], bb[0][1]);
            mma_fp16(acc[0][1], ah[0], bb[0][2], bb[0][3]);
            mma_fp16(acc[1][1], ah[1], bb[0][2], bb[0][3]);
            LDM4(al[0], mAl + oA);
            mma_fp16(acc[0][2], ah[0], bb[1][0], bb[1][1]);
            mma_fp16(acc[1][2], ah[1], bb[1][0], bb[1][1]);
            mma_fp16(acc[0][3], ah[0], bb[1][2], bb[1][3]);
            mma_fp16(acc[1][3], ah[1], bb[1][2], bb[1][3]);
            LDM4(al[1], mAl + oA + 1024);
            #pragma unroll
            for (int p = 2; p < 4; p++) {
                mma_fp16(acc[0][2 * p],     ah[0], bb[p][0], bb[p][1]);
                mma_fp16(acc[1][2 * p],     ah[1], bb[p][0], bb[p][1]);
                mma_fp16(acc[0][2 * p + 1], ah[0], bb[p][2], bb[p][3]);
                mma_fp16(acc[1][2 * p + 1], ah[1], bb[p][2], bb[p][3]);
            }
            // pass 2: lo*hi; overwrite Bh[p] with B-lo[p] after last use
            #pragma unroll
            for (int p = 0; p < 4; p++) {
                mma_fp16(acc[0][2 * p],     al[0], bb[p][0], bb[p][1]);
                mma_fp16(acc[1][2 * p],     al[1], bb[p][0], bb[p][1]);
                mma_fp16(acc[0][2 * p + 1], al[0], bb[p][2], bb[p][3]);
                mma_fp16(acc[1][2 * p + 1], al[1], bb[p][2], bb[p][3]);
                LDM4(bb[p], mBl + oB + (uint32_t)(p * 1024));
            }
            // pass 3: hi*lo
            #pragma unroll
            for (int p = 0; p < 4; p++) {
                mma_fp16(acc[0][2 * p],     ah[0], bb[p][0], bb[p][1]);
                mma_fp16(acc[1][2 * p],     ah[1], bb[p][0], bb[p][1]);
                mma_fp16(acc[0][2 * p + 1], ah[0], bb[p][2], bb[p][3]);
                mma_fp16(acc[1][2 * p + 1], ah[1], bb[p][2], bb[p][3]);
            }
        }
        stC = (stC == 2) ? 0 : stC + 1;
        stI = (stI == 2) ? 0 : stI + 1;
    }

    // ----- epilogue: acc = 512*dot; exact /512 via fma; reference grid -----
    #pragma unroll
    for (int mt = 0; mt < 2; mt++) {
        int row0 = m0 + wm * 32 + mt * 16 + g;
        int row1 = row0 + 8;
        float s1a = g_s1[row0];
        float s1b = g_s1[row1];
        unsigned long long k0 = 0xFFFFFFFFFFFFFFFFULL;
        unsigned long long k1 = 0xFFFFFFFFFFFFFFFFULL;
        #pragma unroll
        for (int nt = 0; nt < 8; nt++) {
            int nb = n0 + wn * 64 + nt * 8 + 2 * tig;
            #pragma unroll
            for (int q = 0; q < 2; q++) {
                int n = nb + q;
                float s2v = __ldg(&g_s2[n]);
                {
                    float f = __fmaf_rn(-0.00390625f, acc[mt][nt][q], s1a) + s2v;
                    unsigned u = __float_as_uint(f);
                    u = (u & 0x80000000u) ? ~u : (u | 0x80000000u);
                    unsigned long long key = ((unsigned long long)u << 32) | (unsigned)n;
                    k0 = k0 < key ? k0 : key;
                }
                {
                    float f = __fmaf_rn(-0.00390625f, acc[mt][nt][q + 2], s1b) + s2v;
                    unsigned u = __float_as_uint(f);
                    u = (u & 0x80000000u) ? ~u : (u | 0x80000000u);
                    unsigned long long key = ((unsigned long long)u << 32) | (unsigned)n;
                    k1 = k1 < key ? k1 : key;
                }
            }
        }
        #pragma unroll
        for (int o = 1; o <= 2; o <<= 1) {
            unsigned long long t0 = __shfl_xor_sync(0xffffffffu, k0, o);
            unsigned long long t1 = __shfl_xor_sync(0xffffffffu, k1, o);
            k0 = k0 < t0 ? k0 : t0;
            k1 = k1 < t1 ? k1 : t1;
        }
        if (tig == 0) {
            atomicMin(&g_best[row0], k0);
            atomicMin(&g_best[row1], k1);
        }
    }
}

// ---------------- gather z_q_st, indices, loss ----------------
__global__ void gather_kernel(const float* __restrict__ z,
                              const float* __restrict__ cb,
                              float* __restrict__ out, int out_size) {
    __shared__ float sm[32][257];
    __shared__ int   sidx[32];
    __shared__ double ssum[8];
    int m0 = blockIdx.x * 32;
    int b  = m0 >> 11;
    int t0 = m0 & 2047;
    int tid = threadIdx.x;

    if (tid < 32) {
        int idx = (int)(g_best[m0 + tid] & 0xFFFFFFFFULL);
        sidx[tid] = idx;
        if (out_size >= ZQ_ELEMS + BT_)
            out[ZQ_ELEMS + m0 + tid] = (float)idx;
    }
    __syncthreads();
    for (int r = 0; r < 32; r++)
        sm[r][tid] = cb[(size_t)sidx[r] * D_ + tid];
    __syncthreads();

    int tt = tid & 31, dp = tid >> 5;
    double lsum = 0.0;
    #pragma unroll 4
    for (int it = 0; it < 32; it++) {
        int d = dp * 32 + it;
        size_t oi = ((size_t)b * D_ + d) * T_ + t0 + tt;
        float zq = sm[tt][d];
        float zv = z[oi];
        float r  = zq - zv;
        out[oi]  = zv + r;
        lsum += (double)r * r;
    }
    #pragma unroll
    for (int o = 16; o; o >>= 1) lsum += __shfl_xor_sync(0xffffffffu, lsum, o);
    if (tt == 0) ssum[dp] = lsum;
    __syncthreads();
    if (tid == 0) {
        double tot = 0.0;
        #pragma unroll
        for (int p = 0; p < 8; p++) tot += ssum[p];
        atomicAdd(&g_loss, tot);
    }
}

__global__ void finalize_kernel(float* __restrict__ out, int out_size) {
    if (out_size >= ZQ_ELEMS + BT_ + 1)
        out[ZQ_ELEMS + BT_] = (float)(1.1 * g_loss / (double)ZQ_ELEMS);
}

// ---------------- launch ----------------
extern "C" void kernel_launch(void* const* d_in, const int* in_sizes, int n_in,
                              void* d_out, int out_size) {
    const float* z  = (const float*)d_in[0];
    const float* cb = (const float*)d_in[1];
    if (n_in >= 2 && in_sizes[0] == K_ * D_ && in_sizes[1] == ZQ_ELEMS) {
        const float* t = z; z = cb; cb = t;
    }
    float* out = (float*)d_out;

    cudaFuncSetAttribute(dist_mma_kernel,
                         cudaFuncAttributeMaxDynamicSharedMemorySize, SMEM_BYTES);

    split_cb_kernel<<<K_ / 8, 256>>>(cb);
    split_z_kernel<<<BT_ / 32, 256>>>(z);

    dim3 grid(K_ / 128, BT_ / 128);   // (64, 128) = 8192 CTAs
    dist_mma_kernel<<<grid, 256, SMEM_BYTES>>>();

    gather_kernel<<<BT_ / 32, 256>>>(z, cb, out, out_size);
    finalize_kernel<<<1, 1>>>(out, out_size);
}